// round 13
// baseline (speedup 1.0000x reference)
#include <cuda_runtime.h>
#include <cuda_bf16.h>
#include <cuda_fp16.h>
#include <cstdint>

// ---------------------------------------------------------------------------
// GAT 3-layer pipeline on GB300 (sm_103a).  R10:
//  - layer-3 projection fused into agg4<1> epilogue (both half-warps hold the
//    full 128-dim output after the shfl-16 combine: half0 projects W3, half1
//    projects rW3 -> l3gemm launch + h2 round-trip eliminated)
//  - W1 split inlined into gemm1 B-load (prepW1 launch eliminated)
//  - agg3 edge loop unrolled x2 (overlap consecutive edges' loads)
//  - keeps: pipelined agg4, FFMA2 accum, fp16 feat, dual-B GEMM, forked CSR
// ---------------------------------------------------------------------------

#define MAXN 50176
#define MAXE 860160

__device__ int      g_cnt[MAXN];
__device__ int      g_off[MAXN + 1];
__device__ int      g_pos[MAXN];
__device__ int      g_bflag[64];
__device__ int      g_csrc[MAXE];
__device__ __half   g_featH[MAXN * 128];
__device__ float    g_res [MAXN * 128];
__device__ uint32_t g_h1hi[MAXN * 64], g_h1lo[MAXN * 64];
__device__ float    g_el  [MAXN * 4];
__device__ float    g_er  [MAXN * 4];
__device__ float    g_f3p [MAXN * 8];
__device__ float    g_er3p[MAXN * 8];
__device__ float    g_rb3 [MAXN];
__device__ uint32_t g_w2hi[128 * 64], g_w2lo[128 * 64];
__device__ uint32_t g_r2hi[128 * 64], g_r2lo[128 * 64];

// --------------------------- helpers ---------------------------------------

__device__ __forceinline__ void split2(float x, float y, uint32_t& h, uint32_t& l) {
    __nv_bfloat162 hh = __floats2bfloat162_rn(x, y);          // low 16 = x
    float hx = __bfloat162float(hh.x), hy = __bfloat162float(hh.y);
    __nv_bfloat162 ll = __floats2bfloat162_rn(x - hx, y - hy);
    h = *reinterpret_cast<uint32_t*>(&hh);
    l = *reinterpret_cast<uint32_t*>(&ll);
}

__device__ __forceinline__ void mma16816(float* c, const uint32_t* a,
                                         uint32_t b0, uint32_t b1) {
    asm volatile(
        "mma.sync.aligned.m16n8k16.row.col.f32.bf16.bf16.f32 "
        "{%0,%1,%2,%3}, {%4,%5,%6,%7}, {%8,%9}, {%0,%1,%2,%3};\n"
        : "+f"(c[0]), "+f"(c[1]), "+f"(c[2]), "+f"(c[3])
        : "r"(a[0]), "r"(a[1]), "r"(a[2]), "r"(a[3]), "r"(b0), "r"(b1));
}

// half2 -> f32x2 convert + packed FFMA2 accumulate (acc += f32x2(h2) * eq2)
__device__ __forceinline__ void hacc(uint64_t& acc, uint32_t h2, uint64_t eq2) {
    asm("{\n\t"
        ".reg .f16 a, b;\n\t"
        ".reg .f32 fa, fb;\n\t"
        ".reg .b64 f;\n\t"
        "mov.b32 {a, b}, %1;\n\t"
        "cvt.f32.f16 fa, a;\n\t"
        "cvt.f32.f16 fb, b;\n\t"
        "mov.b64 f, {fa, fb};\n\t"
        "fma.rn.f32x2 %0, f, %2, %0;\n\t"
        "}" : "+l"(acc) : "r"(h2), "l"(eq2));
}

__global__ void k_prepW2(const float* __restrict__ W2, const float* __restrict__ rW2) {
    int idx = blockIdx.x * 256 + threadIdx.x;
    if (idx >= 16384) return;
    const float* W = (idx < 8192) ? W2 : rW2;
    uint32_t* H = (idx < 8192) ? g_w2hi : g_r2hi;
    uint32_t* L = (idx < 8192) ? g_w2lo : g_r2lo;
    int local = idx & 8191;
    int kk = local >> 7, nn = local & 127;
    float w0 = W[(2 * kk) * 128 + nn];
    float w1 = W[(2 * kk + 1) * 128 + nn];
    uint32_t h, l;
    split2(w0, w1, h, l);
    H[nn * 64 + kk] = h;
    L[nn * 64 + kk] = l;
}

// ------------------------------ CSR build ---------------------------------

__global__ void k_hist(const int* __restrict__ dst, int E) {
    if (blockIdx.x == 0 && threadIdx.x < 64) g_bflag[threadIdx.x] = 0;
    int i = (blockIdx.x * blockDim.x + threadIdx.x) * 4;
    if (i + 3 < E) {
        int4 d = *(const int4*)(dst + i);
        atomicAdd(&g_cnt[d.x], 1);
        atomicAdd(&g_cnt[d.y], 1);
        atomicAdd(&g_cnt[d.z], 1);
        atomicAdd(&g_cnt[d.w], 1);
    } else {
        for (int j = i; j < E; j++) atomicAdd(&g_cnt[dst[j]], 1);
    }
}

// single-pass exclusive scan with lookback (all blocks resident).
__global__ void k_scan2(int n, int E) {
    __shared__ int ws[32];
    __shared__ int pre_s;
    int t = threadIdx.x, lane = t & 31, wid = t >> 5, b = blockIdx.x;
    int i = b * 1024 + t;
    int v = (i < n) ? g_cnt[i] : 0;
    int x = v;
    #pragma unroll
    for (int d = 1; d < 32; d <<= 1) {
        int y = __shfl_up_sync(0xffffffffu, x, d);
        if (lane >= d) x += y;
    }
    if (lane == 31) ws[wid] = x;
    __syncthreads();
    if (wid == 0) {
        int s = ws[lane];
        #pragma unroll
        for (int d = 1; d < 32; d <<= 1) {
            int y = __shfl_up_sync(0xffffffffu, s, d);
            if (lane >= d) s += y;
        }
        ws[lane] = s;
    }
    __syncthreads();
    int incl = x + (wid > 0 ? ws[wid - 1] : 0);
    if (t == 1023) atomicExch(&g_bflag[b], incl + 1);
    if (wid == 0) {
        int s = 0;
        for (int j = lane; j < b; j += 32) {
            int f;
            while ((f = atomicAdd(&g_bflag[j], 0)) == 0) { }
            s += f - 1;
        }
        #pragma unroll
        for (int o = 16; o > 0; o >>= 1) s += __shfl_xor_sync(0xffffffffu, s, o);
        if (lane == 0) pre_s = s;
    }
    __syncthreads();
    if (i < n) {
        int o = incl - v + pre_s;
        g_off[i] = o;
        g_pos[i] = o;
    }
    if (b == 0 && t == 0) g_off[n] = E;
}

// scatter + zero cnt for the next (deterministic) replay
__global__ void k_scatter(const int* __restrict__ src, const int* __restrict__ dst,
                          int E, int n) {
    int gid = blockIdx.x * blockDim.x + threadIdx.x;
    if (gid < n) g_cnt[gid] = 0;
    int i = gid * 4;
    if (i + 3 < E) {
        int4 s = *(const int4*)(src + i);
        int4 d = *(const int4*)(dst + i);
        int p0 = atomicAdd(&g_pos[d.x], 1);
        int p1 = atomicAdd(&g_pos[d.y], 1);
        int p2 = atomicAdd(&g_pos[d.z], 1);
        int p3 = atomicAdd(&g_pos[d.w], 1);
        g_csrc[p0] = s.x; g_csrc[p1] = s.y; g_csrc[p2] = s.z; g_csrc[p3] = s.w;
    } else {
        for (int j = i; j < E; j++) {
            int p = atomicAdd(&g_pos[dst[j]], 1);
            g_csrc[p] = src[j];
        }
    }
}

// ------- layer-1 GEMM: featH = x @ W1 (+el/er), W1 split inlined -----------

__launch_bounds__(256, 2)
__global__ void k_gemm1(const float* __restrict__ A, const float* __restrict__ W1,
                        int M, const float* __restrict__ alv,
                        const float* __restrict__ arv) {
    const int K = 64;
    __shared__ uint32_t sAhi[128 * 20], sAlo[128 * 20];
    __shared__ uint32_t sBhi[128 * 20], sBlo[128 * 20];
    __shared__ float sEl[512], sEr[512], sAl[128], sAr[128];
    const int t = threadIdx.x;
    const int rowBase = blockIdx.x * 128;
    const int wid = t >> 5, lane = t & 31;
    const int mwarp = wid >> 1, nwarp = wid & 1;
    const int g = lane >> 2, tig = lane & 3;

    if (t < 128) { sAl[t] = alv[t]; sAr[t] = arv[t]; }

    float c[2][8][4];
    #pragma unroll
    for (int mi = 0; mi < 2; mi++)
        #pragma unroll
        for (int ni = 0; ni < 8; ni++)
            #pragma unroll
            for (int j = 0; j < 4; j++) c[mi][ni][j] = 0.f;

    for (int k0 = 0; k0 < K; k0 += 32) {
        const int kk0 = k0 >> 1;
        #pragma unroll
        for (int i = 0; i < 4; i++) {
            int idx = t + i * 256;
            int r = idx >> 3, c4 = idx & 7;
            int gr = rowBase + r;
            float4 v = make_float4(0.f, 0.f, 0.f, 0.f);
            if (gr < M) v = *(const float4*)(A + (size_t)gr * K + k0 + c4 * 4);
            uint32_t h0, l0, h1, l1;
            split2(v.x, v.y, h0, l0);
            split2(v.z, v.w, h1, l1);
            int b = r * 20 + c4 * 2;
            sAhi[b] = h0; sAlo[b] = l0;
            sAhi[b + 1] = h1; sAlo[b + 1] = l1;
        }
        // B tile: inline split of W1 (2048 pairs; coalesced over nn)
        #pragma unroll
        for (int i = 0; i < 8; i++) {
            int idx = t + i * 256;
            int j = idx >> 7, nn = idx & 127;
            int kp = kk0 + j;
            float w0 = W1[(2 * kp) * 128 + nn];
            float w1 = W1[(2 * kp + 1) * 128 + nn];
            uint32_t h, l;
            split2(w0, w1, h, l);
            sBhi[nn * 20 + j] = h;
            sBlo[nn * 20 + j] = l;
        }
        __syncthreads();
        #pragma unroll
        for (int ks = 0; ks < 2; ks++) {
            const int ko = ks * 8;
            uint32_t ah[2][4], al_[2][4];
            #pragma unroll
            for (int mi = 0; mi < 2; mi++) {
                int base = (mwarp * 32 + mi * 16 + g) * 20 + ko + tig;
                ah[mi][0] = sAhi[base];        al_[mi][0] = sAlo[base];
                ah[mi][1] = sAhi[base + 160];  al_[mi][1] = sAlo[base + 160];
                ah[mi][2] = sAhi[base + 4];    al_[mi][2] = sAlo[base + 4];
                ah[mi][3] = sAhi[base + 164];  al_[mi][3] = sAlo[base + 164];
            }
            #pragma unroll
            for (int ni = 0; ni < 8; ni++) {
                int bb = (nwarp * 64 + ni * 8 + g) * 20 + ko + tig;
                uint32_t bh0 = sBhi[bb], bh1 = sBhi[bb + 4];
                uint32_t bl0 = sBlo[bb], bl1 = sBlo[bb + 4];
                #pragma unroll
                for (int mi = 0; mi < 2; mi++) {
                    mma16816(c[mi][ni], ah[mi], bh0, bh1);
                    mma16816(c[mi][ni], ah[mi], bl0, bl1);
                    mma16816(c[mi][ni], al_[mi], bh0, bh1);
                }
            }
        }
        __syncthreads();
    }
    #pragma unroll
    for (int mi = 0; mi < 2; mi++) {
        int r0 = rowBase + mwarp * 32 + mi * 16 + g;
        #pragma unroll
        for (int ni = 0; ni < 8; ni++) {
            int col = nwarp * 64 + ni * 8 + tig * 2;
            if (r0 < M)
                *(__half2*)(g_featH + (size_t)r0 * 128 + col) =
                    __floats2half2_rn(c[mi][ni][0], c[mi][ni][1]);
            if (r0 + 8 < M)
                *(__half2*)(g_featH + (size_t)(r0 + 8) * 128 + col) =
                    __floats2half2_rn(c[mi][ni][2], c[mi][ni][3]);
        }
    }
    #pragma unroll
    for (int mi = 0; mi < 2; mi++) {
        float pel[2][2] = {{0.f, 0.f}, {0.f, 0.f}};
        float per_[2][2] = {{0.f, 0.f}, {0.f, 0.f}};
        #pragma unroll
        for (int ni = 0; ni < 8; ni++) {
            int col = nwarp * 64 + ni * 8 + tig * 2;
            int hh = ni >> 2;
            float a0 = sAl[col], a1 = sAl[col + 1];
            float r0 = sAr[col], r1 = sAr[col + 1];
            pel[0][hh] += c[mi][ni][0] * a0 + c[mi][ni][1] * a1;
            per_[0][hh] += c[mi][ni][0] * r0 + c[mi][ni][1] * r1;
            pel[1][hh] += c[mi][ni][2] * a0 + c[mi][ni][3] * a1;
            per_[1][hh] += c[mi][ni][2] * r0 + c[mi][ni][3] * r1;
        }
        #pragma unroll
        for (int gg = 0; gg < 2; gg++)
            #pragma unroll
            for (int hh = 0; hh < 2; hh++) {
                float v = pel[gg][hh], w = per_[gg][hh];
                v += __shfl_xor_sync(0xffffffffu, v, 1);
                v += __shfl_xor_sync(0xffffffffu, v, 2);
                w += __shfl_xor_sync(0xffffffffu, w, 1);
                w += __shfl_xor_sync(0xffffffffu, w, 2);
                if (tig == 0) {
                    int r = mwarp * 32 + mi * 16 + g + gg * 8;
                    sEl[r * 4 + nwarp * 2 + hh] = v;
                    sEr[r * 4 + nwarp * 2 + hh] = w;
                }
            }
    }
    __syncthreads();
    #pragma unroll
    for (int i0 = 0; i0 < 2; i0++) {
        int i = t + i0 * 256;
        int gr = rowBase + (i >> 2);
        if (gr < M) {
            g_el[gr * 4 + (i & 3)] = sEl[i];
            g_er[gr * 4 + (i & 3)] = sEr[i];
        }
    }
}

// --------- layer-2 dual GEMM: featH = h1@W2 (+el/er), res = h1@rW2 ---------

#define ASTRIDE 68

__launch_bounds__(256, 2)
__global__ void k_gemm2dual(int M, const float* __restrict__ alv,
                            const float* __restrict__ arv) {
    extern __shared__ uint32_t sm[];
    uint32_t* sAhi = sm;
    uint32_t* sAlo = sAhi + 128 * ASTRIDE;
    uint32_t* sBhi = sAlo + 128 * ASTRIDE;
    uint32_t* sBlo = sBhi + 128 * 20;
    float* sEl = (float*)(sBlo + 128 * 20);
    float* sEr = sEl + 512;
    float* sAl = sEr + 512;
    float* sAr = sAl + 128;

    const int t = threadIdx.x;
    const int rowBase = blockIdx.x * 128;
    const int wid = t >> 5, lane = t & 31;
    const int mwarp = wid >> 1, nwarp = wid & 1;
    const int g = lane >> 2, tig = lane & 3;

    if (t < 128) { sAl[t] = alv[t]; sAr[t] = arv[t]; }

    const uint4* Ahi = (const uint4*)g_h1hi;
    const uint4* Alo = (const uint4*)g_h1lo;
    #pragma unroll
    for (int i = 0; i < 8; i++) {
        int idx = t + i * 256;
        int r = idx >> 4, j = idx & 15;
        int gr = rowBase + r;
        uint4 vh = make_uint4(0u, 0u, 0u, 0u), vl = make_uint4(0u, 0u, 0u, 0u);
        if (gr < M) {
            vh = Ahi[(size_t)gr * 16 + j];
            vl = Alo[(size_t)gr * 16 + j];
        }
        *(uint4*)&sAhi[r * ASTRIDE + j * 4] = vh;
        *(uint4*)&sAlo[r * ASTRIDE + j * 4] = vl;
    }

    #pragma unroll
    for (int bmat = 0; bmat < 2; bmat++) {
        const uint32_t* Whi = bmat ? g_r2hi : g_w2hi;
        const uint32_t* Wlo = bmat ? g_r2lo : g_w2lo;
        float c[2][8][4];
        #pragma unroll
        for (int mi = 0; mi < 2; mi++)
            #pragma unroll
            for (int ni = 0; ni < 8; ni++)
                #pragma unroll
                for (int j = 0; j < 4; j++) c[mi][ni][j] = 0.f;

        for (int kt = 0; kt < 4; kt++) {
            __syncthreads();
            #pragma unroll
            for (int i = 0; i < 2; i++) {
                int idx = t + i * 256;
                int nn = idx >> 2, j = (idx & 3) * 4;
                uint4 vh = *(const uint4*)(Whi + nn * 64 + kt * 16 + j);
                uint4 vl = *(const uint4*)(Wlo + nn * 64 + kt * 16 + j);
                int b = nn * 20 + j;
                sBhi[b] = vh.x; sBhi[b + 1] = vh.y; sBhi[b + 2] = vh.z; sBhi[b + 3] = vh.w;
                sBlo[b] = vl.x; sBlo[b + 1] = vl.y; sBlo[b + 2] = vl.z; sBlo[b + 3] = vl.w;
            }
            __syncthreads();
            #pragma unroll
            for (int ks = 0; ks < 2; ks++) {
                const int ko = ks * 8;
                uint32_t ah[2][4], al_[2][4];
                #pragma unroll
                for (int mi = 0; mi < 2; mi++) {
                    int base = (mwarp * 32 + mi * 16 + g) * ASTRIDE + kt * 16 + ko + tig;
                    ah[mi][0] = sAhi[base];                   al_[mi][0] = sAlo[base];
                    ah[mi][1] = sAhi[base + 8 * ASTRIDE];     al_[mi][1] = sAlo[base + 8 * ASTRIDE];
                    ah[mi][2] = sAhi[base + 4];               al_[mi][2] = sAlo[base + 4];
                    ah[mi][3] = sAhi[base + 8 * ASTRIDE + 4]; al_[mi][3] = sAlo[base + 8 * ASTRIDE + 4];
                }
                #pragma unroll
                for (int ni = 0; ni < 8; ni++) {
                    int bb = (nwarp * 64 + ni * 8 + g) * 20 + ko + tig;
                    uint32_t bh0 = sBhi[bb], bh1 = sBhi[bb + 4];
                    uint32_t bl0 = sBlo[bb], bl1 = sBlo[bb + 4];
                    #pragma unroll
                    for (int mi = 0; mi < 2; mi++) {
                        mma16816(c[mi][ni], ah[mi], bh0, bh1);
                        mma16816(c[mi][ni], ah[mi], bl0, bl1);
                        mma16816(c[mi][ni], al_[mi], bh0, bh1);
                    }
                }
            }
        }

        if (bmat == 0) {
            #pragma unroll
            for (int mi = 0; mi < 2; mi++) {
                int r0 = rowBase + mwarp * 32 + mi * 16 + g;
                #pragma unroll
                for (int ni = 0; ni < 8; ni++) {
                    int col = nwarp * 64 + ni * 8 + tig * 2;
                    if (r0 < M)
                        *(__half2*)(g_featH + (size_t)r0 * 128 + col) =
                            __floats2half2_rn(c[mi][ni][0], c[mi][ni][1]);
                    if (r0 + 8 < M)
                        *(__half2*)(g_featH + (size_t)(r0 + 8) * 128 + col) =
                            __floats2half2_rn(c[mi][ni][2], c[mi][ni][3]);
                }
            }
            #pragma unroll
            for (int mi = 0; mi < 2; mi++) {
                float pel[2][2] = {{0.f, 0.f}, {0.f, 0.f}};
                float per_[2][2] = {{0.f, 0.f}, {0.f, 0.f}};
                #pragma unroll
                for (int ni = 0; ni < 8; ni++) {
                    int col = nwarp * 64 + ni * 8 + tig * 2;
                    int hh = ni >> 2;
                    float a0 = sAl[col], a1 = sAl[col + 1];
                    float r0 = sAr[col], r1 = sAr[col + 1];
                    pel[0][hh] += c[mi][ni][0] * a0 + c[mi][ni][1] * a1;
                    per_[0][hh] += c[mi][ni][0] * r0 + c[mi][ni][1] * r1;
                    pel[1][hh] += c[mi][ni][2] * a0 + c[mi][ni][3] * a1;
                    per_[1][hh] += c[mi][ni][2] * r0 + c[mi][ni][3] * r1;
                }
                #pragma unroll
                for (int gg = 0; gg < 2; gg++)
                    #pragma unroll
                    for (int hh = 0; hh < 2; hh++) {
                        float v = pel[gg][hh], w = per_[gg][hh];
                        v += __shfl_xor_sync(0xffffffffu, v, 1);
                        v += __shfl_xor_sync(0xffffffffu, v, 2);
                        w += __shfl_xor_sync(0xffffffffu, w, 1);
                        w += __shfl_xor_sync(0xffffffffu, w, 2);
                        if (tig == 0) {
                            int r = mwarp * 32 + mi * 16 + g + gg * 8;
                            sEl[r * 4 + nwarp * 2 + hh] = v;
                            sEr[r * 4 + nwarp * 2 + hh] = w;
                        }
                    }
            }
            __syncthreads();
            #pragma unroll
            for (int i0 = 0; i0 < 2; i0++) {
                int i = t + i0 * 256;
                int gr = rowBase + (i >> 2);
                if (gr < M) {
                    g_el[gr * 4 + (i & 3)] = sEl[i];
                    g_er[gr * 4 + (i & 3)] = sEr[i];
                }
            }
        } else {
            #pragma unroll
            for (int mi = 0; mi < 2; mi++) {
                int r0 = rowBase + mwarp * 32 + mi * 16 + g;
                #pragma unroll
                for (int ni = 0; ni < 8; ni++) {
                    int col = nwarp * 64 + ni * 8 + tig * 2;
                    if (r0 < M)
                        *(float2*)(g_res + (size_t)r0 * 128 + col) =
                            make_float2(c[mi][ni][0], c[mi][ni][1]);
                    if (r0 + 8 < M)
                        *(float2*)(g_res + (size_t)(r0 + 8) * 128 + col) =
                            make_float2(c[mi][ni][2], c[mi][ni][3]);
                }
            }
        }
    }
}

// ---------- warp-per-node aggregation, H=4 D=32, pipelined -----------------
// MODE 0: L1 (no res; pre-split bf16 h1 out).
// MODE 1: L2 (res; layer-3 projection fused: after the shfl-16 combine both
//         half-warps hold the full 128-dim output; half0 projects W3, half1
//         projects rW3; f3p/er3p/rb3 written directly, no h2 buffer).

template <int MODE>
__launch_bounds__(256)
__global__ void k_agg4(const float4* __restrict__ res4,
                       const float4* __restrict__ bias4,
                       const float* __restrict__ W3, const float* __restrict__ rW3,
                       const float* __restrict__ ar3, const float* __restrict__ b3,
                       int n) {
    __shared__ float sW3[768], sR3[768];
    if (MODE == 1) {
        for (int i = threadIdx.x; i < 768; i += 256) {
            sW3[i] = W3[i];
            sR3[i] = rW3[i];
        }
        __syncthreads();
    }
    int node = blockIdx.x * 8 + (threadIdx.x >> 5);
    if (node >= n) return;
    const int lane = threadIdx.x & 31;
    const int h = lane & 3, eo = lane >> 2;
    const int li = lane & 15, half = lane >> 4, hd = li >> 2;
    int rs = g_off[node], re = g_off[node + 1];
    float er_h = g_er[node * 4 + h];
    const uint4* featH4 = (const uint4*)g_featH;

    uint64_t acc[4];
    #pragma unroll
    for (int j = 0; j < 4; j++) acc[j] = 0ull;      // f32x2 {0,0}
    float den = 0.f;

    int nbatch = (re - rs + 7) >> 3;
    int s_cur = 0; float ee_cur = 0.f;
    {
        int e = rs + eo;
        if (e < re) {
            int s = g_csrc[e];
            float v = g_el[s * 4 + h] + er_h;
            v = v > 0.f ? v : 0.2f * v;
            s_cur = s; ee_cur = __expf(v); den += ee_cur;
        }
    }
    for (int i = 0; i < nbatch; i++) {
        int s_nxt = 0; float ee_nxt = 0.f;
        {
            int e = rs + (i + 1) * 8 + eo;
            if (e < re) {
                int s = g_csrc[e];
                float v = g_el[s * 4 + h] + er_h;
                v = v > 0.f ? v : 0.2f * v;
                s_nxt = s; ee_nxt = __expf(v); den += ee_nxt;
            }
        }
        #pragma unroll
        for (int q = 0; q < 4; q++) {
            int esl = (q * 2 + half) * 4;
            int   sq  = __shfl_sync(0xffffffffu, s_cur, esl);
            float eqf = __shfl_sync(0xffffffffu, ee_cur, esl + hd);
            uint64_t eq2;
            asm("mov.b64 %0, {%1, %1};" : "=l"(eq2) : "f"(eqf));
            uint4 u = featH4[(size_t)sq * 16 + li];
            hacc(acc[0], u.x, eq2);
            hacc(acc[1], u.y, eq2);
            hacc(acc[2], u.z, eq2);
            hacc(acc[3], u.w, eq2);
        }
        s_cur = s_nxt; ee_cur = ee_nxt;
    }

    float a[8];
    #pragma unroll
    for (int j = 0; j < 4; j++)
        asm("mov.b64 {%0, %1}, %2;" : "=f"(a[2 * j]), "=f"(a[2 * j + 1]) : "l"(acc[j]));

    den += __shfl_xor_sync(0xffffffffu, den, 16);
    den += __shfl_xor_sync(0xffffffffu, den, 8);
    den += __shfl_xor_sync(0xffffffffu, den, 4);
    float inv = 1.f / __shfl_sync(0xffffffffu, den, hd);
    #pragma unroll
    for (int j = 0; j < 8; j++)
        a[j] += __shfl_xor_sync(0xffffffffu, a[j], 16);

    if (MODE == 0) {
        if (half == 0) {
            float4 b0 = bias4[2 * li], b1 = bias4[2 * li + 1];
            float o[8];
            o[0] = a[0] * inv + b0.x; o[1] = a[1] * inv + b0.y;
            o[2] = a[2] * inv + b0.z; o[3] = a[3] * inv + b0.w;
            o[4] = a[4] * inv + b1.x; o[5] = a[5] * inv + b1.y;
            o[6] = a[6] * inv + b1.z; o[7] = a[7] * inv + b1.w;
            #pragma unroll
            for (int j = 0; j < 8; j++) o[j] = fmaxf(o[j], 0.f);
            uint32_t H[4], L[4];
            split2(o[0], o[1], H[0], L[0]);
            split2(o[2], o[3], H[1], L[1]);
            split2(o[4], o[5], H[2], L[2]);
            split2(o[6], o[7], H[3], L[3]);
            ((uint4*)g_h1hi)[(size_t)node * 16 + li] = make_uint4(H[0], H[1], H[2], H[3]);
            ((uint4*)g_h1lo)[(size_t)node * 16 + li] = make_uint4(L[0], L[1], L[2], L[3]);
        }
    } else {
        // all 32 lanes: finish output dims [8*li .. 8*li+7]
        float4 b0 = bias4[2 * li], b1 = bias4[2 * li + 1];
        float4 r0 = res4[(size_t)node * 32 + 2 * li];
        float4 r1 = res4[(size_t)node * 32 + 2 * li + 1];
        float o[8];
        o[0] = a[0] * inv + b0.x + r0.x; o[1] = a[1] * inv + b0.y + r0.y;
        o[2] = a[2] * inv + b0.z + r0.z; o[3] = a[3] * inv + b0.w + r0.w;
        o[4] = a[4] * inv + b1.x + r1.x; o[5] = a[5] * inv + b1.y + r1.y;
        o[6] = a[6] * inv + b1.z + r1.z; o[7] = a[7] * inv + b1.w + r1.w;
        #pragma unroll
        for (int j = 0; j < 8; j++) o[j] = fmaxf(o[j], 0.f);
        // half0 -> W3 projection (f3); half1 -> rW3 projection (residual)
        const float* sWsel = half ? sR3 : sW3;
        const int c0 = li * 8;
        float p[6];
        #pragma unroll
        for (int j = 0; j < 6; j++) {
            float s = 0.f;
            #pragma unroll
            for (int d = 0; d < 8; d++)
                s = fmaf(o[d], sWsel[(c0 + d) * 6 + j], s);
            p[j] = s;
        }
        #pragma unroll
        for (int j = 0; j < 6; j++) {
            #pragma unroll
            for (int off = 8; off > 0; off >>= 1)
                p[j] += __shfl_xor_sync(0xffffffffu, p[j], off);
        }
        if (lane == 0) {
            ((float4*)g_f3p)[node * 2]     = make_float4(p[0], p[1], p[2], p[3]);
            ((float4*)g_f3p)[node * 2 + 1] = make_float4(p[4], p[5], 0.f, 0.f);
            ((float4*)g_er3p)[node * 2]     = make_float4(p[0] * ar3[0], p[1] * ar3[1],
                                                          p[2] * ar3[2], p[3] * ar3[3]);
            ((float4*)g_er3p)[node * 2 + 1] = make_float4(p[4] * ar3[4], p[5] * ar3[5],
                                                          0.f, 0.f);
        } else if (lane == 16) {
            float rb = 0.f;
            #pragma unroll
            for (int j = 0; j < 6; j++) rb += p[j] + b3[j];
            g_rb3[node] = rb;
        }
    }
}

// --------- layer 3 aggregation (H=6, D=1) + head mean, single pass ---------

__global__ void k_agg3(const float* __restrict__ al3, float* __restrict__ out, int n) {
    int node = blockIdx.x * 8 + (threadIdx.x >> 5);
    if (node >= n) return;
    int lane = threadIdx.x & 31;
    int rs = g_off[node], re = g_off[node + 1];
    float al[6];
    #pragma unroll
    for (int j = 0; j < 6; j++) al[j] = al3[j];
    float4 e0 = *(const float4*)(g_er3p + (size_t)node * 8);
    float4 e1 = *(const float4*)(g_er3p + (size_t)node * 8 + 4);
    float erh[6] = {e0.x, e0.y, e0.z, e0.w, e1.x, e1.y};

    float acc[6], den[6];
    #pragma unroll
    for (int j = 0; j < 6; j++) { acc[j] = 0.f; den[j] = 0.f; }
    #pragma unroll 2
    for (int e = rs + lane; e < re; e += 32) {
        int s = g_csrc[e];
        float4 f0 = *(const float4*)(g_f3p + (size_t)s * 8);
        float4 f1 = *(const float4*)(g_f3p + (size_t)s * 8 + 4);
        float f[6] = {f0.x, f0.y, f0.z, f0.w, f1.x, f1.y};
        #pragma unroll
        for (int j = 0; j < 6; j++) {
            float v = fmaf(f[j], al[j], erh[j]);
            v = v > 0.f ? v : 0.2f * v;
            float ee = __expf(v);
            den[j] += ee;
            acc[j] = fmaf(ee, f[j], acc[j]);
        }
    }
    #pragma unroll
    for (int j = 0; j < 6; j++) {
        #pragma unroll
        for (int o = 16; o > 0; o >>= 1) {
            acc[j] += __shfl_xor_sync(0xffffffffu, acc[j], o);
            den[j] += __shfl_xor_sync(0xffffffffu, den[j], o);
        }
    }
    if (lane == 0) {
        float o_ = 0.f;
        #pragma unroll
        for (int j = 0; j < 6; j++) o_ += acc[j] / den[j];
        out[node] = (o_ + g_rb3[node]) * (1.f / 6.f);
    }
}

// ------------------------------- launcher ----------------------------------

#define G2_SMEM ((128 * ASTRIDE * 2 + 128 * 20 * 2) * 4 + (512 * 2 + 128 * 2) * 4)

extern "C" void kernel_launch(void* const* d_in, const int* in_sizes, int n_in,
                              void* d_out, int out_size) {
    const float* x   = (const float*)d_in[0];
    const int*   src = (const int*)  d_in[1];
    const int*   dst = (const int*)  d_in[2];
    const float* W1  = (const float*)d_in[3];
    const float* al1 = (const float*)d_in[4];
    const float* ar1 = (const float*)d_in[5];
    const float* b1  = (const float*)d_in[6];
    const float* W2  = (const float*)d_in[7];
    const float* al2 = (const float*)d_in[8];
    const float* ar2 = (const float*)d_in[9];
    const float* b2  = (const float*)d_in[10];
    const float* rW2 = (const float*)d_in[11];
    const float* W3  = (const float*)d_in[12];
    const float* al3 = (const float*)d_in[13];
    const float* ar3 = (const float*)d_in[14];
    const float* b3  = (const float*)d_in[15];
    const float* rW3 = (const float*)d_in[16];
    int n = in_sizes[0] / 64;
    int E = in_sizes[1];
    float* out = (float*)d_out;

    float* res;
    cudaGetSymbolAddress((void**)&res, g_res);

    static cudaStream_t s2 = nullptr, s3 = nullptr;
    static cudaEvent_t evFork = nullptr, evJoin = nullptr, evPrep2 = nullptr;
    if (!s2) {
        cudaStreamCreateWithFlags(&s2, cudaStreamNonBlocking);
        cudaStreamCreateWithFlags(&s3, cudaStreamNonBlocking);
        cudaEventCreateWithFlags(&evFork, cudaEventDisableTiming);
        cudaEventCreateWithFlags(&evJoin, cudaEventDisableTiming);
        cudaEventCreateWithFlags(&evPrep2, cudaEventDisableTiming);
        cudaFuncSetAttribute(k_gemm2dual,
                             cudaFuncAttributeMaxDynamicSharedMemorySize, G2_SMEM);
    }

    int nb = (n + 1023) / 1024;
    int gb = (n + 127) / 128;
    int ab = (n + 7) / 8;

    // --- fork: CSR on s2, prepW2 on s3, gemm1 (inline W1) on main ---
    cudaEventRecord(evFork, 0);
    cudaStreamWaitEvent(s2, evFork, 0);
    cudaStreamWaitEvent(s3, evFork, 0);

    k_hist   <<<(E + 1023) / 1024, 256, 0, s2>>>(dst, E);
    k_scan2  <<<nb, 1024, 0, s2>>>(n, E);
    k_scatter<<<(E + 1023) / 1024, 256, 0, s2>>>(src, dst, E, n);
    cudaEventRecord(evJoin, s2);

    k_prepW2<<<64, 256, 0, s3>>>(W2, rW2);
    cudaEventRecord(evPrep2, s3);

    k_gemm1<<<gb, 256>>>(x, W1, n, al1, ar1);

    cudaStreamWaitEvent(0, evJoin, 0);

    // --- layer 1 aggregate -> pre-split h1 pairs ---
    k_agg4<0><<<ab, 256>>>((const float4*)nullptr, (const float4*)b1,
                           nullptr, nullptr, nullptr, nullptr, n);

    cudaStreamWaitEvent(0, evPrep2, 0);

    // --- layer 2: dual GEMM (+el/er), aggregate + fused layer-3 projection ---
    k_gemm2dual<<<gb, 256, G2_SMEM>>>(n, al2, ar2);
    k_agg4<1><<<ab, 256>>>((const float4*)res, (const float4*)b2,
                           W3, rW3, ar3, b3, n);

    // --- layer 3 aggregation -> output ---
    k_agg3<<<ab, 256>>>(al3, out, n);
}

// round 14
// speedup vs baseline: 1.0921x; 1.0921x over previous
#include <cuda_runtime.h>
#include <cuda_bf16.h>
#include <cuda_fp16.h>
#include <cstdint>

// ---------------------------------------------------------------------------
// GAT 3-layer pipeline on GB300 (sm_103a).  R11:
//  - REVERT R10's l3-fusion-into-agg4 + inline-W1 (2nd confirmation: epilogue
//    fusion starves the latency-bound aggregator of occupancy; rule: hot
//    aggregator stays lean)
//  - agg4: __launch_bounds__(256, 6) to lift occupancy 50% -> ~75%
//  - agg3: edge loop unrolled x2
//  - keeps: pipelined agg4 logits, FFMA2 accum, fp16 feat + fp16 h2,
//    dual-B GEMM, forked CSR, lookback scan
// ---------------------------------------------------------------------------

#define MAXN 50176
#define MAXE 860160

__device__ int      g_cnt[MAXN];
__device__ int      g_off[MAXN + 1];
__device__ int      g_pos[MAXN];
__device__ int      g_bflag[64];
__device__ int      g_csrc[MAXE];
__device__ __half   g_featH[MAXN * 128];
__device__ __half   g_h2H  [MAXN * 128];
__device__ float    g_res [MAXN * 128];
__device__ uint32_t g_h1hi[MAXN * 64], g_h1lo[MAXN * 64];
__device__ float    g_el  [MAXN * 4];
__device__ float    g_er  [MAXN * 4];
__device__ float    g_f3p [MAXN * 8];
__device__ float    g_er3p[MAXN * 8];
__device__ float    g_rb3 [MAXN];
__device__ uint32_t g_w1hi[128 * 32], g_w1lo[128 * 32];
__device__ uint32_t g_w2hi[128 * 64], g_w2lo[128 * 64];
__device__ uint32_t g_r2hi[128 * 64], g_r2lo[128 * 64];

// --------------------------- helpers ---------------------------------------

__device__ __forceinline__ void split2(float x, float y, uint32_t& h, uint32_t& l) {
    __nv_bfloat162 hh = __floats2bfloat162_rn(x, y);          // low 16 = x
    float hx = __bfloat162float(hh.x), hy = __bfloat162float(hh.y);
    __nv_bfloat162 ll = __floats2bfloat162_rn(x - hx, y - hy);
    h = *reinterpret_cast<uint32_t*>(&hh);
    l = *reinterpret_cast<uint32_t*>(&ll);
}

__device__ __forceinline__ void mma16816(float* c, const uint32_t* a,
                                         uint32_t b0, uint32_t b1) {
    asm volatile(
        "mma.sync.aligned.m16n8k16.row.col.f32.bf16.bf16.f32 "
        "{%0,%1,%2,%3}, {%4,%5,%6,%7}, {%8,%9}, {%0,%1,%2,%3};\n"
        : "+f"(c[0]), "+f"(c[1]), "+f"(c[2]), "+f"(c[3])
        : "r"(a[0]), "r"(a[1]), "r"(a[2]), "r"(a[3]), "r"(b0), "r"(b1));
}

// half2 -> f32x2 convert + packed FFMA2 accumulate (acc += f32x2(h2) * eq2)
__device__ __forceinline__ void hacc(uint64_t& acc, uint32_t h2, uint64_t eq2) {
    asm("{\n\t"
        ".reg .f16 a, b;\n\t"
        ".reg .f32 fa, fb;\n\t"
        ".reg .b64 f;\n\t"
        "mov.b32 {a, b}, %1;\n\t"
        "cvt.f32.f16 fa, a;\n\t"
        "cvt.f32.f16 fb, b;\n\t"
        "mov.b64 f, {fa, fb};\n\t"
        "fma.rn.f32x2 %0, f, %2, %0;\n\t"
        "}" : "+l"(acc) : "r"(h2), "l"(eq2));
}

__global__ void k_prepW1(const float* __restrict__ W1) {
    int idx = blockIdx.x * 256 + threadIdx.x;
    if (idx >= 4096) return;
    int kk = idx >> 7, nn = idx & 127;
    float w0 = W1[(2 * kk) * 128 + nn];
    float w1 = W1[(2 * kk + 1) * 128 + nn];
    uint32_t h, l;
    split2(w0, w1, h, l);
    g_w1hi[nn * 32 + kk] = h;
    g_w1lo[nn * 32 + kk] = l;
}

__global__ void k_prepW2(const float* __restrict__ W2, const float* __restrict__ rW2) {
    int idx = blockIdx.x * 256 + threadIdx.x;
    if (idx >= 16384) return;
    const float* W = (idx < 8192) ? W2 : rW2;
    uint32_t* H = (idx < 8192) ? g_w2hi : g_r2hi;
    uint32_t* L = (idx < 8192) ? g_w2lo : g_r2lo;
    int local = idx & 8191;
    int kk = local >> 7, nn = local & 127;
    float w0 = W[(2 * kk) * 128 + nn];
    float w1 = W[(2 * kk + 1) * 128 + nn];
    uint32_t h, l;
    split2(w0, w1, h, l);
    H[nn * 64 + kk] = h;
    L[nn * 64 + kk] = l;
}

// ------------------------------ CSR build ---------------------------------

__global__ void k_hist(const int* __restrict__ dst, int E) {
    if (blockIdx.x == 0 && threadIdx.x < 64) g_bflag[threadIdx.x] = 0;
    int i = (blockIdx.x * blockDim.x + threadIdx.x) * 4;
    if (i + 3 < E) {
        int4 d = *(const int4*)(dst + i);
        atomicAdd(&g_cnt[d.x], 1);
        atomicAdd(&g_cnt[d.y], 1);
        atomicAdd(&g_cnt[d.z], 1);
        atomicAdd(&g_cnt[d.w], 1);
    } else {
        for (int j = i; j < E; j++) atomicAdd(&g_cnt[dst[j]], 1);
    }
}

// single-pass exclusive scan with lookback (all blocks resident).
__global__ void k_scan2(int n, int E) {
    __shared__ int ws[32];
    __shared__ int pre_s;
    int t = threadIdx.x, lane = t & 31, wid = t >> 5, b = blockIdx.x;
    int i = b * 1024 + t;
    int v = (i < n) ? g_cnt[i] : 0;
    int x = v;
    #pragma unroll
    for (int d = 1; d < 32; d <<= 1) {
        int y = __shfl_up_sync(0xffffffffu, x, d);
        if (lane >= d) x += y;
    }
    if (lane == 31) ws[wid] = x;
    __syncthreads();
    if (wid == 0) {
        int s = ws[lane];
        #pragma unroll
        for (int d = 1; d < 32; d <<= 1) {
            int y = __shfl_up_sync(0xffffffffu, s, d);
            if (lane >= d) s += y;
        }
        ws[lane] = s;
    }
    __syncthreads();
    int incl = x + (wid > 0 ? ws[wid - 1] : 0);
    if (t == 1023) atomicExch(&g_bflag[b], incl + 1);
    if (wid == 0) {
        int s = 0;
        for (int j = lane; j < b; j += 32) {
            int f;
            while ((f = atomicAdd(&g_bflag[j], 0)) == 0) { }
            s += f - 1;
        }
        #pragma unroll
        for (int o = 16; o > 0; o >>= 1) s += __shfl_xor_sync(0xffffffffu, s, o);
        if (lane == 0) pre_s = s;
    }
    __syncthreads();
    if (i < n) {
        int o = incl - v + pre_s;
        g_off[i] = o;
        g_pos[i] = o;
    }
    if (b == 0 && t == 0) g_off[n] = E;
}

// scatter + zero cnt for the next (deterministic) replay
__global__ void k_scatter(const int* __restrict__ src, const int* __restrict__ dst,
                          int E, int n) {
    int gid = blockIdx.x * blockDim.x + threadIdx.x;
    if (gid < n) g_cnt[gid] = 0;
    int i = gid * 4;
    if (i + 3 < E) {
        int4 s = *(const int4*)(src + i);
        int4 d = *(const int4*)(dst + i);
        int p0 = atomicAdd(&g_pos[d.x], 1);
        int p1 = atomicAdd(&g_pos[d.y], 1);
        int p2 = atomicAdd(&g_pos[d.z], 1);
        int p3 = atomicAdd(&g_pos[d.w], 1);
        g_csrc[p0] = s.x; g_csrc[p1] = s.y; g_csrc[p2] = s.z; g_csrc[p3] = s.w;
    } else {
        for (int j = i; j < E; j++) {
            int p = atomicAdd(&g_pos[dst[j]], 1);
            g_csrc[p] = src[j];
        }
    }
}

// ---------------- layer-1 GEMM: featH[M x 128] = x @ W1 + el/er ------------

__launch_bounds__(256, 2)
__global__ void k_gemm1(const float* __restrict__ A, int M,
                        const float* __restrict__ alv,
                        const float* __restrict__ arv) {
    const int K = 64, NP = 32;
    __shared__ uint32_t sAhi[128 * 20], sAlo[128 * 20];
    __shared__ uint32_t sBhi[128 * 20], sBlo[128 * 20];
    __shared__ float sEl[512], sEr[512], sAl[128], sAr[128];
    const int t = threadIdx.x;
    const int rowBase = blockIdx.x * 128;
    const int wid = t >> 5, lane = t & 31;
    const int mwarp = wid >> 1, nwarp = wid & 1;
    const int g = lane >> 2, tig = lane & 3;

    if (t < 128) { sAl[t] = alv[t]; sAr[t] = arv[t]; }

    float c[2][8][4];
    #pragma unroll
    for (int mi = 0; mi < 2; mi++)
        #pragma unroll
        for (int ni = 0; ni < 8; ni++)
            #pragma unroll
            for (int j = 0; j < 4; j++) c[mi][ni][j] = 0.f;

    for (int k0 = 0; k0 < K; k0 += 32) {
        const int kk0 = k0 >> 1;
        #pragma unroll
        for (int i = 0; i < 4; i++) {
            int idx = t + i * 256;
            int r = idx >> 3, c4 = idx & 7;
            int gr = rowBase + r;
            float4 v = make_float4(0.f, 0.f, 0.f, 0.f);
            if (gr < M) v = *(const float4*)(A + (size_t)gr * K + k0 + c4 * 4);
            uint32_t h0, l0, h1, l1;
            split2(v.x, v.y, h0, l0);
            split2(v.z, v.w, h1, l1);
            int b = r * 20 + c4 * 2;
            sAhi[b] = h0; sAlo[b] = l0;
            sAhi[b + 1] = h1; sAlo[b + 1] = l1;
        }
        #pragma unroll
        for (int i = 0; i < 2; i++) {
            int idx = t + i * 256;
            int nn = idx >> 2, j = (idx & 3) * 4;
            uint4 vh = *(const uint4*)(g_w1hi + nn * NP + kk0 + j);
            uint4 vl = *(const uint4*)(g_w1lo + nn * NP + kk0 + j);
            int b = nn * 20 + j;
            sBhi[b] = vh.x; sBhi[b + 1] = vh.y; sBhi[b + 2] = vh.z; sBhi[b + 3] = vh.w;
            sBlo[b] = vl.x; sBlo[b + 1] = vl.y; sBlo[b + 2] = vl.z; sBlo[b + 3] = vl.w;
        }
        __syncthreads();
        #pragma unroll
        for (int ks = 0; ks < 2; ks++) {
            const int ko = ks * 8;
            uint32_t ah[2][4], al_[2][4];
            #pragma unroll
            for (int mi = 0; mi < 2; mi++) {
                int base = (mwarp * 32 + mi * 16 + g) * 20 + ko + tig;
                ah[mi][0] = sAhi[base];        al_[mi][0] = sAlo[base];
                ah[mi][1] = sAhi[base + 160];  al_[mi][1] = sAlo[base + 160];
                ah[mi][2] = sAhi[base + 4];    al_[mi][2] = sAlo[base + 4];
                ah[mi][3] = sAhi[base + 164];  al_[mi][3] = sAlo[base + 164];
            }
            #pragma unroll
            for (int ni = 0; ni < 8; ni++) {
                int bb = (nwarp * 64 + ni * 8 + g) * 20 + ko + tig;
                uint32_t bh0 = sBhi[bb], bh1 = sBhi[bb + 4];
                uint32_t bl0 = sBlo[bb], bl1 = sBlo[bb + 4];
                #pragma unroll
                for (int mi = 0; mi < 2; mi++) {
                    mma16816(c[mi][ni], ah[mi], bh0, bh1);
                    mma16816(c[mi][ni], ah[mi], bl0, bl1);
                    mma16816(c[mi][ni], al_[mi], bh0, bh1);
                }
            }
        }
        __syncthreads();
    }
    #pragma unroll
    for (int mi = 0; mi < 2; mi++) {
        int r0 = rowBase + mwarp * 32 + mi * 16 + g;
        #pragma unroll
        for (int ni = 0; ni < 8; ni++) {
            int col = nwarp * 64 + ni * 8 + tig * 2;
            if (r0 < M)
                *(__half2*)(g_featH + (size_t)r0 * 128 + col) =
                    __floats2half2_rn(c[mi][ni][0], c[mi][ni][1]);
            if (r0 + 8 < M)
                *(__half2*)(g_featH + (size_t)(r0 + 8) * 128 + col) =
                    __floats2half2_rn(c[mi][ni][2], c[mi][ni][3]);
        }
    }
    #pragma unroll
    for (int mi = 0; mi < 2; mi++) {
        float pel[2][2] = {{0.f, 0.f}, {0.f, 0.f}};
        float per_[2][2] = {{0.f, 0.f}, {0.f, 0.f}};
        #pragma unroll
        for (int ni = 0; ni < 8; ni++) {
            int col = nwarp * 64 + ni * 8 + tig * 2;
            int hh = ni >> 2;
            float a0 = sAl[col], a1 = sAl[col + 1];
            float r0 = sAr[col], r1 = sAr[col + 1];
            pel[0][hh] += c[mi][ni][0] * a0 + c[mi][ni][1] * a1;
            per_[0][hh] += c[mi][ni][0] * r0 + c[mi][ni][1] * r1;
            pel[1][hh] += c[mi][ni][2] * a0 + c[mi][ni][3] * a1;
            per_[1][hh] += c[mi][ni][2] * r0 + c[mi][ni][3] * r1;
        }
        #pragma unroll
        for (int gg = 0; gg < 2; gg++)
            #pragma unroll
            for (int hh = 0; hh < 2; hh++) {
                float v = pel[gg][hh], w = per_[gg][hh];
                v += __shfl_xor_sync(0xffffffffu, v, 1);
                v += __shfl_xor_sync(0xffffffffu, v, 2);
                w += __shfl_xor_sync(0xffffffffu, w, 1);
                w += __shfl_xor_sync(0xffffffffu, w, 2);
                if (tig == 0) {
                    int r = mwarp * 32 + mi * 16 + g + gg * 8;
                    sEl[r * 4 + nwarp * 2 + hh] = v;
                    sEr[r * 4 + nwarp * 2 + hh] = w;
                }
            }
    }
    __syncthreads();
    #pragma unroll
    for (int i0 = 0; i0 < 2; i0++) {
        int i = t + i0 * 256;
        int gr = rowBase + (i >> 2);
        if (gr < M) {
            g_el[gr * 4 + (i & 3)] = sEl[i];
            g_er[gr * 4 + (i & 3)] = sEr[i];
        }
    }
}

// --------- layer-2 dual GEMM: featH = h1@W2 (+el/er), res = h1@rW2 ---------

#define ASTRIDE 68

__launch_bounds__(256, 2)
__global__ void k_gemm2dual(int M, const float* __restrict__ alv,
                            const float* __restrict__ arv) {
    extern __shared__ uint32_t sm[];
    uint32_t* sAhi = sm;
    uint32_t* sAlo = sAhi + 128 * ASTRIDE;
    uint32_t* sBhi = sAlo + 128 * ASTRIDE;
    uint32_t* sBlo = sBhi + 128 * 20;
    float* sEl = (float*)(sBlo + 128 * 20);
    float* sEr = sEl + 512;
    float* sAl = sEr + 512;
    float* sAr = sAl + 128;

    const int t = threadIdx.x;
    const int rowBase = blockIdx.x * 128;
    const int wid = t >> 5, lane = t & 31;
    const int mwarp = wid >> 1, nwarp = wid & 1;
    const int g = lane >> 2, tig = lane & 3;

    if (t < 128) { sAl[t] = alv[t]; sAr[t] = arv[t]; }

    const uint4* Ahi = (const uint4*)g_h1hi;
    const uint4* Alo = (const uint4*)g_h1lo;
    #pragma unroll
    for (int i = 0; i < 8; i++) {
        int idx = t + i * 256;
        int r = idx >> 4, j = idx & 15;
        int gr = rowBase + r;
        uint4 vh = make_uint4(0u, 0u, 0u, 0u), vl = make_uint4(0u, 0u, 0u, 0u);
        if (gr < M) {
            vh = Ahi[(size_t)gr * 16 + j];
            vl = Alo[(size_t)gr * 16 + j];
        }
        *(uint4*)&sAhi[r * ASTRIDE + j * 4] = vh;
        *(uint4*)&sAlo[r * ASTRIDE + j * 4] = vl;
    }

    #pragma unroll
    for (int bmat = 0; bmat < 2; bmat++) {
        const uint32_t* Whi = bmat ? g_r2hi : g_w2hi;
        const uint32_t* Wlo = bmat ? g_r2lo : g_w2lo;
        float c[2][8][4];
        #pragma unroll
        for (int mi = 0; mi < 2; mi++)
            #pragma unroll
            for (int ni = 0; ni < 8; ni++)
                #pragma unroll
                for (int j = 0; j < 4; j++) c[mi][ni][j] = 0.f;

        for (int kt = 0; kt < 4; kt++) {
            __syncthreads();
            #pragma unroll
            for (int i = 0; i < 2; i++) {
                int idx = t + i * 256;
                int nn = idx >> 2, j = (idx & 3) * 4;
                uint4 vh = *(const uint4*)(Whi + nn * 64 + kt * 16 + j);
                uint4 vl = *(const uint4*)(Wlo + nn * 64 + kt * 16 + j);
                int b = nn * 20 + j;
                sBhi[b] = vh.x; sBhi[b + 1] = vh.y; sBhi[b + 2] = vh.z; sBhi[b + 3] = vh.w;
                sBlo[b] = vl.x; sBlo[b + 1] = vl.y; sBlo[b + 2] = vl.z; sBlo[b + 3] = vl.w;
            }
            __syncthreads();
            #pragma unroll
            for (int ks = 0; ks < 2; ks++) {
                const int ko = ks * 8;
                uint32_t ah[2][4], al_[2][4];
                #pragma unroll
                for (int mi = 0; mi < 2; mi++) {
                    int base = (mwarp * 32 + mi * 16 + g) * ASTRIDE + kt * 16 + ko + tig;
                    ah[mi][0] = sAhi[base];                   al_[mi][0] = sAlo[base];
                    ah[mi][1] = sAhi[base + 8 * ASTRIDE];     al_[mi][1] = sAlo[base + 8 * ASTRIDE];
                    ah[mi][2] = sAhi[base + 4];               al_[mi][2] = sAlo[base + 4];
                    ah[mi][3] = sAhi[base + 8 * ASTRIDE + 4]; al_[mi][3] = sAlo[base + 8 * ASTRIDE + 4];
                }
                #pragma unroll
                for (int ni = 0; ni < 8; ni++) {
                    int bb = (nwarp * 64 + ni * 8 + g) * 20 + ko + tig;
                    uint32_t bh0 = sBhi[bb], bh1 = sBhi[bb + 4];
                    uint32_t bl0 = sBlo[bb], bl1 = sBlo[bb + 4];
                    #pragma unroll
                    for (int mi = 0; mi < 2; mi++) {
                        mma16816(c[mi][ni], ah[mi], bh0, bh1);
                        mma16816(c[mi][ni], ah[mi], bl0, bl1);
                        mma16816(c[mi][ni], al_[mi], bh0, bh1);
                    }
                }
            }
        }

        if (bmat == 0) {
            #pragma unroll
            for (int mi = 0; mi < 2; mi++) {
                int r0 = rowBase + mwarp * 32 + mi * 16 + g;
                #pragma unroll
                for (int ni = 0; ni < 8; ni++) {
                    int col = nwarp * 64 + ni * 8 + tig * 2;
                    if (r0 < M)
                        *(__half2*)(g_featH + (size_t)r0 * 128 + col) =
                            __floats2half2_rn(c[mi][ni][0], c[mi][ni][1]);
                    if (r0 + 8 < M)
                        *(__half2*)(g_featH + (size_t)(r0 + 8) * 128 + col) =
                            __floats2half2_rn(c[mi][ni][2], c[mi][ni][3]);
                }
            }
            #pragma unroll
            for (int mi = 0; mi < 2; mi++) {
                float pel[2][2] = {{0.f, 0.f}, {0.f, 0.f}};
                float per_[2][2] = {{0.f, 0.f}, {0.f, 0.f}};
                #pragma unroll
                for (int ni = 0; ni < 8; ni++) {
                    int col = nwarp * 64 + ni * 8 + tig * 2;
                    int hh = ni >> 2;
                    float a0 = sAl[col], a1 = sAl[col + 1];
                    float r0 = sAr[col], r1 = sAr[col + 1];
                    pel[0][hh] += c[mi][ni][0] * a0 + c[mi][ni][1] * a1;
                    per_[0][hh] += c[mi][ni][0] * r0 + c[mi][ni][1] * r1;
                    pel[1][hh] += c[mi][ni][2] * a0 + c[mi][ni][3] * a1;
                    per_[1][hh] += c[mi][ni][2] * r0 + c[mi][ni][3] * r1;
                }
                #pragma unroll
                for (int gg = 0; gg < 2; gg++)
                    #pragma unroll
                    for (int hh = 0; hh < 2; hh++) {
                        float v = pel[gg][hh], w = per_[gg][hh];
                        v += __shfl_xor_sync(0xffffffffu, v, 1);
                        v += __shfl_xor_sync(0xffffffffu, v, 2);
                        w += __shfl_xor_sync(0xffffffffu, w, 1);
                        w += __shfl_xor_sync(0xffffffffu, w, 2);
                        if (tig == 0) {
                            int r = mwarp * 32 + mi * 16 + g + gg * 8;
                            sEl[r * 4 + nwarp * 2 + hh] = v;
                            sEr[r * 4 + nwarp * 2 + hh] = w;
                        }
                    }
            }
            __syncthreads();
            #pragma unroll
            for (int i0 = 0; i0 < 2; i0++) {
                int i = t + i0 * 256;
                int gr = rowBase + (i >> 2);
                if (gr < M) {
                    g_el[gr * 4 + (i & 3)] = sEl[i];
                    g_er[gr * 4 + (i & 3)] = sEr[i];
                }
            }
        } else {
            #pragma unroll
            for (int mi = 0; mi < 2; mi++) {
                int r0 = rowBase + mwarp * 32 + mi * 16 + g;
                #pragma unroll
                for (int ni = 0; ni < 8; ni++) {
                    int col = nwarp * 64 + ni * 8 + tig * 2;
                    if (r0 < M)
                        *(float2*)(g_res + (size_t)r0 * 128 + col) =
                            make_float2(c[mi][ni][0], c[mi][ni][1]);
                    if (r0 + 8 < M)
                        *(float2*)(g_res + (size_t)(r0 + 8) * 128 + col) =
                            make_float2(c[mi][ni][2], c[mi][ni][3]);
                }
            }
        }
    }
}

// ---------- warp-per-node aggregation, H=4 D=32, pipelined -----------------
// MODE 0: L1 (no res; pre-split bf16 h1 out). MODE 1: L2 (res; fp16 h2 out).
// min 6 blocks/SM for occupancy on this latency-bound kernel.

template <int MODE>
__launch_bounds__(256, 6)
__global__ void k_agg4(const float4* __restrict__ res4,
                       const float4* __restrict__ bias4, int n) {
    int node = blockIdx.x * 8 + (threadIdx.x >> 5);
    if (node >= n) return;
    const int lane = threadIdx.x & 31;
    const int h = lane & 3, eo = lane >> 2;
    const int li = lane & 15, half = lane >> 4, hd = li >> 2;
    int rs = g_off[node], re = g_off[node + 1];
    float er_h = g_er[node * 4 + h];
    const uint4* featH4 = (const uint4*)g_featH;

    uint64_t acc[4];
    #pragma unroll
    for (int j = 0; j < 4; j++) acc[j] = 0ull;      // f32x2 {0,0}
    float den = 0.f;

    int nbatch = (re - rs + 7) >> 3;
    int s_cur = 0; float ee_cur = 0.f;
    {
        int e = rs + eo;
        if (e < re) {
            int s = g_csrc[e];
            float v = g_el[s * 4 + h] + er_h;
            v = v > 0.f ? v : 0.2f * v;
            s_cur = s; ee_cur = __expf(v); den += ee_cur;
        }
    }
    for (int i = 0; i < nbatch; i++) {
        int s_nxt = 0; float ee_nxt = 0.f;
        {
            int e = rs + (i + 1) * 8 + eo;
            if (e < re) {
                int s = g_csrc[e];
                float v = g_el[s * 4 + h] + er_h;
                v = v > 0.f ? v : 0.2f * v;
                s_nxt = s; ee_nxt = __expf(v); den += ee_nxt;
            }
        }
        #pragma unroll
        for (int q = 0; q < 4; q++) {
            int esl = (q * 2 + half) * 4;
            int   sq  = __shfl_sync(0xffffffffu, s_cur, esl);
            float eqf = __shfl_sync(0xffffffffu, ee_cur, esl + hd);
            uint64_t eq2;
            asm("mov.b64 %0, {%1, %1};" : "=l"(eq2) : "f"(eqf));
            uint4 u = featH4[(size_t)sq * 16 + li];
            hacc(acc[0], u.x, eq2);
            hacc(acc[1], u.y, eq2);
            hacc(acc[2], u.z, eq2);
            hacc(acc[3], u.w, eq2);
        }
        s_cur = s_nxt; ee_cur = ee_nxt;
    }

    float a[8];
    #pragma unroll
    for (int j = 0; j < 4; j++)
        asm("mov.b64 {%0, %1}, %2;" : "=f"(a[2 * j]), "=f"(a[2 * j + 1]) : "l"(acc[j]));

    den += __shfl_xor_sync(0xffffffffu, den, 16);
    den += __shfl_xor_sync(0xffffffffu, den, 8);
    den += __shfl_xor_sync(0xffffffffu, den, 4);
    float inv = 1.f / __shfl_sync(0xffffffffu, den, hd);
    #pragma unroll
    for (int j = 0; j < 8; j++)
        a[j] += __shfl_xor_sync(0xffffffffu, a[j], 16);

    if (half == 0) {
        float4 b0 = bias4[2 * li], b1 = bias4[2 * li + 1];
        float o[8];
        o[0] = a[0] * inv + b0.x; o[1] = a[1] * inv + b0.y;
        o[2] = a[2] * inv + b0.z; o[3] = a[3] * inv + b0.w;
        o[4] = a[4] * inv + b1.x; o[5] = a[5] * inv + b1.y;
        o[6] = a[6] * inv + b1.z; o[7] = a[7] * inv + b1.w;
        if (MODE == 1) {
            float4 r0 = res4[(size_t)node * 32 + 2 * li];
            float4 r1 = res4[(size_t)node * 32 + 2 * li + 1];
            o[0] += r0.x; o[1] += r0.y; o[2] += r0.z; o[3] += r0.w;
            o[4] += r1.x; o[5] += r1.y; o[6] += r1.z; o[7] += r1.w;
        }
        #pragma unroll
        for (int j = 0; j < 8; j++) o[j] = fmaxf(o[j], 0.f);
        if (MODE == 1) {
            uint4 uo;
            __half2* op = (__half2*)&uo;
            op[0] = __floats2half2_rn(o[0], o[1]);
            op[1] = __floats2half2_rn(o[2], o[3]);
            op[2] = __floats2half2_rn(o[4], o[5]);
            op[3] = __floats2half2_rn(o[6], o[7]);
            ((uint4*)g_h2H)[(size_t)node * 16 + li] = uo;
        } else {
            uint32_t H[4], L[4];
            split2(o[0], o[1], H[0], L[0]);
            split2(o[2], o[3], H[1], L[1]);
            split2(o[4], o[5], H[2], L[2]);
            split2(o[6], o[7], H[3], L[3]);
            ((uint4*)g_h1hi)[(size_t)node * 16 + li] = make_uint4(H[0], H[1], H[2], H[3]);
            ((uint4*)g_h1lo)[(size_t)node * 16 + li] = make_uint4(L[0], L[1], L[2], L[3]);
        }
    }
}

// ---------------- layer 3: small GEMM from fp16 h2 -------------------------

__global__ void k_l3gemm(const float* __restrict__ W3,
                         const float* __restrict__ rW3, const float* __restrict__ ar3,
                         const float* __restrict__ b3, int n) {
    __shared__ float sW[768], sR[768];
    int t = threadIdx.x;
    for (int i = t; i < 768; i += 256) { sW[i] = W3[i]; sR[i] = rW3[i]; }
    __syncthreads();
    int node = blockIdx.x * 256 + t;
    if (node >= n) return;
    const uint4* hr = ((const uint4*)g_h2H) + (size_t)node * 16;
    float acc[6] = {0.f, 0.f, 0.f, 0.f, 0.f, 0.f};
    float rac[6] = {0.f, 0.f, 0.f, 0.f, 0.f, 0.f};
    #pragma unroll 4
    for (int k8 = 0; k8 < 16; k8++) {
        uint4 u = hr[k8];
        const __half2* hp = (const __half2*)&u;
        float2 a0 = __half22float2(hp[0]);
        float2 a1 = __half22float2(hp[1]);
        float2 a2 = __half22float2(hp[2]);
        float2 a3 = __half22float2(hp[3]);
        float a[8] = {a0.x, a0.y, a1.x, a1.y, a2.x, a2.y, a3.x, a3.y};
        int k = k8 * 8;
        #pragma unroll
        for (int j = 0; j < 6; j++) {
            float s1 = 0.f, s2 = 0.f;
            #pragma unroll
            for (int d = 0; d < 8; d++) {
                s1 = fmaf(a[d], sW[(k + d) * 6 + j], s1);
                s2 = fmaf(a[d], sR[(k + d) * 6 + j], s2);
            }
            acc[j] += s1;
            rac[j] += s2;
        }
    }
    float rb = 0.f;
    #pragma unroll
    for (int j = 0; j < 6; j++) {
        g_f3p [node * 8 + j] = acc[j];
        g_er3p[node * 8 + j] = acc[j] * ar3[j];
        rb += rac[j] + b3[j];
    }
    g_f3p [node * 8 + 6] = 0.f; g_f3p [node * 8 + 7] = 0.f;
    g_er3p[node * 8 + 6] = 0.f; g_er3p[node * 8 + 7] = 0.f;
    g_rb3[node] = rb;
}

// --------- layer 3 aggregation (H=6, D=1) + head mean, single pass ---------

__global__ void k_agg3(const float* __restrict__ al3, float* __restrict__ out, int n) {
    int node = blockIdx.x * 8 + (threadIdx.x >> 5);
    if (node >= n) return;
    int lane = threadIdx.x & 31;
    int rs = g_off[node], re = g_off[node + 1];
    float al[6];
    #pragma unroll
    for (int j = 0; j < 6; j++) al[j] = al3[j];
    float4 e0 = *(const float4*)(g_er3p + (size_t)node * 8);
    float4 e1 = *(const float4*)(g_er3p + (size_t)node * 8 + 4);
    float erh[6] = {e0.x, e0.y, e0.z, e0.w, e1.x, e1.y};

    float acc[6], den[6];
    #pragma unroll
    for (int j = 0; j < 6; j++) { acc[j] = 0.f; den[j] = 0.f; }
    #pragma unroll 2
    for (int e = rs + lane; e < re; e += 32) {
        int s = g_csrc[e];
        float4 f0 = *(const float4*)(g_f3p + (size_t)s * 8);
        float4 f1 = *(const float4*)(g_f3p + (size_t)s * 8 + 4);
        float f[6] = {f0.x, f0.y, f0.z, f0.w, f1.x, f1.y};
        #pragma unroll
        for (int j = 0; j < 6; j++) {
            float v = fmaf(f[j], al[j], erh[j]);
            v = v > 0.f ? v : 0.2f * v;
            float ee = __expf(v);
            den[j] += ee;
            acc[j] = fmaf(ee, f[j], acc[j]);
        }
    }
    #pragma unroll
    for (int j = 0; j < 6; j++) {
        #pragma unroll
        for (int o = 16; o > 0; o >>= 1) {
            acc[j] += __shfl_xor_sync(0xffffffffu, acc[j], o);
            den[j] += __shfl_xor_sync(0xffffffffu, den[j], o);
        }
    }
    if (lane == 0) {
        float o_ = 0.f;
        #pragma unroll
        for (int j = 0; j < 6; j++) o_ += acc[j] / den[j];
        out[node] = (o_ + g_rb3[node]) * (1.f / 6.f);
    }
}

// ------------------------------- launcher ----------------------------------

#define G2_SMEM ((128 * ASTRIDE * 2 + 128 * 20 * 2) * 4 + (512 * 2 + 128 * 2) * 4)

extern "C" void kernel_launch(void* const* d_in, const int* in_sizes, int n_in,
                              void* d_out, int out_size) {
    const float* x   = (const float*)d_in[0];
    const int*   src = (const int*)  d_in[1];
    const int*   dst = (const int*)  d_in[2];
    const float* W1  = (const float*)d_in[3];
    const float* al1 = (const float*)d_in[4];
    const float* ar1 = (const float*)d_in[5];
    const float* b1  = (const float*)d_in[6];
    const float* W2  = (const float*)d_in[7];
    const float* al2 = (const float*)d_in[8];
    const float* ar2 = (const float*)d_in[9];
    const float* b2  = (const float*)d_in[10];
    const float* rW2 = (const float*)d_in[11];
    const float* W3  = (const float*)d_in[12];
    const float* al3 = (const float*)d_in[13];
    const float* ar3 = (const float*)d_in[14];
    const float* b3  = (const float*)d_in[15];
    const float* rW3 = (const float*)d_in[16];
    int n = in_sizes[0] / 64;
    int E = in_sizes[1];
    float* out = (float*)d_out;

    float* res;
    cudaGetSymbolAddress((void**)&res, g_res);

    static cudaStream_t s2 = nullptr, s3 = nullptr;
    static cudaEvent_t evFork = nullptr, evJoin = nullptr, evPrep2 = nullptr;
    if (!s2) {
        cudaStreamCreateWithFlags(&s2, cudaStreamNonBlocking);
        cudaStreamCreateWithFlags(&s3, cudaStreamNonBlocking);
        cudaEventCreateWithFlags(&evFork, cudaEventDisableTiming);
        cudaEventCreateWithFlags(&evJoin, cudaEventDisableTiming);
        cudaEventCreateWithFlags(&evPrep2, cudaEventDisableTiming);
        cudaFuncSetAttribute(k_gemm2dual,
                             cudaFuncAttributeMaxDynamicSharedMemorySize, G2_SMEM);
    }

    int nb = (n + 1023) / 1024;
    int gb = (n + 127) / 128;
    int ab = (n + 7) / 8;

    // --- fork: CSR on s2, prepW2 on s3, prepW1 + GEMM1 on main ---
    cudaEventRecord(evFork, 0);
    cudaStreamWaitEvent(s2, evFork, 0);
    cudaStreamWaitEvent(s3, evFork, 0);

    k_hist   <<<(E + 1023) / 1024, 256, 0, s2>>>(dst, E);
    k_scan2  <<<nb, 1024, 0, s2>>>(n, E);
    k_scatter<<<(E + 1023) / 1024, 256, 0, s2>>>(src, dst, E, n);
    cudaEventRecord(evJoin, s2);

    k_prepW2<<<64, 256, 0, s3>>>(W2, rW2);
    cudaEventRecord(evPrep2, s3);

    k_prepW1<<<16, 256>>>(W1);
    k_gemm1<<<gb, 256>>>(x, n, al1, ar1);

    cudaStreamWaitEvent(0, evJoin, 0);

    // --- layer 1 aggregate -> pre-split h1 pairs ---
    k_agg4<0><<<ab, 256>>>((const float4*)nullptr, (const float4*)b1, n);

    cudaStreamWaitEvent(0, evPrep2, 0);

    // --- layer 2: dual GEMM (+el/er), aggregate -> h2 (fp16) ---
    k_gemm2dual<<<gb, 256, G2_SMEM>>>(n, al2, ar2);
    k_agg4<1><<<ab, 256>>>((const float4*)res, (const float4*)b2, n);

    // --- layer 3: projection + aggregation -> output ---
    k_l3gemm<<<(n + 255) / 256, 256>>>(W3, rW3, ar3, b3, n);
    k_agg3<<<ab, 256>>>(al3, out, n);
}